// round 14
// baseline (speedup 1.0000x reference)
#include <cuda_runtime.h>
#include <stdint.h>

// out[i,:] = W[idx[i],:]  idx:[32768] i32, W:[8192,512] f32, out:[32768,512] f32
//
// Bucket-dedup gather, 2 kernels. R12 measured: dedup cut fabric traffic as
// predicted, but the store loop was a serial pos-load->store chain (30us,
// issue 8.7%). Fix: front-batch ALL bucket-position loads unconditionally
// (in-bounds; values beyond cnt unused) so 16 LDGs issue back-to-back, then
// all streaming stores issue independently (v + pos[] in registers).

static constexpr int N_ROWS  = 32768;
static constexpr int N_E     = 8192;
static constexpr int VEC_ROW = 128;   // 128 float4 per 512-float row
static constexpr int CAP     = 32;    // bucket capacity per code
static constexpr int FB      = 16;    // front-batched positions

__device__ int g_cursor[N_E];          // zero-initialized at module load
__device__ int g_bucket[N_E * CAP];

// ---- K1: scatter positions into per-code buckets ------------------------
// Slot order within a bucket is nondeterministic; K2 writes identical row
// data to every position in a bucket -> d_out is value-deterministic.
__global__ void __launch_bounds__(128)
scatter_kernel(const int* __restrict__ idx) {
    const int i = blockIdx.x * blockDim.x + threadIdx.x;   // 0..32767
    const int e = __ldg(&idx[i]);
    const int p = atomicAdd(&g_cursor[e], 1);
    if (p < CAP) g_bucket[e * CAP + p] = i;
}

// ---- K2: per-code broadcast gather + cursor self-clean ------------------
__global__ void __launch_bounds__(VEC_ROW)
gather_bcast_kernel(const float4* __restrict__ table,   // [8192,128] float4
                    float4* __restrict__ out)           // [32768,128] float4
{
    const int e = blockIdx.x;
    const int t = threadIdx.x;

    int cnt = g_cursor[e];              // all threads read (broadcast)...
    __syncthreads();                    // ...ordered before the clean
    if (t == 0) g_cursor[e] = 0;        // self-clean for next graph replay

    if (cnt <= 0) return;
    if (cnt > CAP) cnt = CAP;

    // Row slice into registers (single L2 read per code); independent of the
    // pos loads below - everything issues back-to-back.
    const float4 v = __ldcg(&table[(size_t)e * VEC_ROW + t]);

    // Front-batch bucket positions: FB unconditional, independent loads.
    // Slots >= cnt hold stale-but-in-bounds ints; never consumed.
    int pos[FB];
    #pragma unroll
    for (int p = 0; p < FB; ++p)
        pos[p] = __ldg(&g_bucket[e * CAP + p]);

    // Stores predicated on cnt; all independent (store MLP = cnt).
    #pragma unroll
    for (int p = 0; p < FB; ++p)
        if (p < cnt) __stcs(&out[(size_t)pos[p] * VEC_ROW + t], v);

    // Rare tail (cnt > FB): P(bin>16 | lambda=4) ~ 3e-7; ~0.003 CTAs/grid.
    for (int p = FB; p < cnt; ++p) {
        const int q = __ldg(&g_bucket[e * CAP + p]);
        __stcs(&out[(size_t)q * VEC_ROW + t], v);
    }
}

// ---- launch --------------------------------------------------------------
extern "C" void kernel_launch(void* const* d_in, const int* in_sizes, int n_in,
                              void* d_out, int out_size)
{
    const int*    idx   = (const int*)d_in[0];     // [32768]
    const float4* table = (const float4*)d_in[1];  // [8192,512] f32
    float4*       out   = (float4*)d_out;          // [32768,512] f32

    scatter_kernel     <<<N_ROWS / 128, 128>>>(idx);   // 256 CTAs
    gather_bcast_kernel<<<N_E, VEC_ROW>>>(table, out); // 8192 CTAs
}

// round 15
// speedup vs baseline: 1.7364x; 1.7364x over previous
#include <cuda_runtime.h>
#include <stdint.h>

// out[i, :] = W[idx[i], :]   idx:[32768] int32, W:[8192,512] f32, out:[32768,512] f32
// Flat gather over float4 lanes — best measured design (R3: 15.58us kernel).
// Three flat implementations (LDG MLP4, LDG MLP8+ldcg/stcs, TMA bulk) all
// converge at 15.6-16.7us == mixed R/W L2-path floor for 134MB; dedup variants
// (27-29us) reduced traffic but lost 2x to per-CTA latency. Reverting to R3.

static constexpr int E_DIM    = 512;
static constexpr int VEC_ROW  = E_DIM / 4;   // 128 float4 per row
static constexpr int THREADS  = 256;
static constexpr int UNROLL   = 4;

__global__ void __launch_bounds__(THREADS, 8)
gather_rows_kernel(const int* __restrict__ idx,
                   const float4* __restrict__ table,   // [8192, 128] float4
                   float4* __restrict__ out)           // [32768, 128] float4
{
    const int base = (blockIdx.x * THREADS) * UNROLL + threadIdx.x;

    float4 v[UNROLL];

    // Front-batched independent index + table loads (MLP = 4)
    #pragma unroll
    for (int u = 0; u < UNROLL; ++u) {
        const int g   = base + u * THREADS;
        const int row = g >> 7;              // / 128
        const int t   = g & (VEC_ROW - 1);   // % 128
        const int src = __ldg(&idx[row]);
        v[u] = __ldg(&table[(size_t)src * VEC_ROW + t]);
    }

    #pragma unroll
    for (int u = 0; u < UNROLL; ++u) {
        out[base + u * THREADS] = v[u];
    }
}

extern "C" void kernel_launch(void* const* d_in, const int* in_sizes, int n_in,
                              void* d_out, int out_size)
{
    const int*    idx   = (const int*)d_in[0];      // min_encoding_indices [32768]
    const float4* table = (const float4*)d_in[1];   // embedding_weight [8192,512]
    float4*       out   = (float4*)d_out;           // [32,1024,512] f32

    const int n_rows    = in_sizes[0];              // 32768
    const int total_vec = n_rows * VEC_ROW;         // 4,194,304
    const int per_cta   = THREADS * UNROLL;         // 1024
    const int grid      = total_vec / per_cta;      // 4096 (exact)

    gather_rows_kernel<<<grid, THREADS>>>(idx, table, out);
}